// round 1
// baseline (speedup 1.0000x reference)
#include <cuda_runtime.h>
#include <math.h>

#define HEADS   8
#define DHEAD   32
#define HS      48
#define WS      48
#define HWs     (HS * WS)          // 2304
#define WIN     7
#define RAD     3
#define KN      (WIN * WIN)        // 49
#define TX      16
#define TY      8
#define NTHR    (TX * TY)          // 128
#define HALO_W  (TX + 2 * RAD)     // 22
#define HALO_H  (TY + 2 * RAD)     // 14
#define HALO_PIX (HALO_W * HALO_H) // 308

__global__ __launch_bounds__(NTHR)
void natten2d_kernel(const float* __restrict__ q,
                     const float* __restrict__ k,
                     const float* __restrict__ v,
                     float* __restrict__ out)
{
    // Single halo tile buffer, reused for K then V: 32 ch x 308 px x 4B = 39424 B
    __shared__ float sT[DHEAD][HALO_PIX];

    const int tx = threadIdx.x;
    const int ty = threadIdx.y;
    const int tid = ty * TX + tx;

    const int tileX0 = blockIdx.x * TX;
    const int tileY0 = blockIdx.y * TY;
    const size_t base = (size_t)blockIdx.z * DHEAD * HWs; // (b*HEADS+h)*32 channels

    const float* qp = q + base;
    const float* kp = k + base;
    const float* vp = v + base;
    float* op = out + base;

    const int x = tileX0 + tx;
    const int y = tileY0 + ty;
    const int pix = y * WS + x;

    // ---------------- load K halo ----------------
    #pragma unroll 1
    for (int c = 0; c < DHEAD; c++) {
        const float* kc = kp + c * HWs;
        for (int p = tid; p < HALO_PIX; p += NTHR) {
            int hy = p / HALO_W;
            int hx = p - hy * HALO_W;
            int gy = tileY0 + hy - RAD;
            int gx = tileX0 + hx - RAD;
            float val = 0.0f;
            if (gy >= 0 && gy < HS && gx >= 0 && gx < WS)
                val = kc[gy * WS + gx];
            sT[c][p] = val;
        }
    }
    __syncthreads();

    // ---------------- pass 1: scores = q . k_neighbor ----------------
    float sc[KN];
    #pragma unroll
    for (int n = 0; n < KN; n++) sc[n] = 0.0f;

    const int hbase = ty * HALO_W + tx; // neighbor n lives at hbase + dy*HALO_W + dx

    #pragma unroll 1
    for (int c = 0; c < DHEAD; c++) {
        float qc = qp[c * HWs + pix];
        const float* kb = &sT[c][hbase];
        #pragma unroll
        for (int n = 0; n < KN; n++) {
            sc[n] = fmaf(qc, kb[(n / WIN) * HALO_W + (n % WIN)], sc[n]);
        }
    }

    // ---------------- mask + scale + softmax (registers) ----------------
    const float scale = 0.17677669529663687f; // 1/sqrt(32)
    float m = -1e30f;
    #pragma unroll
    for (int n = 0; n < KN; n++) {
        int gy = y + (n / WIN) - RAD;
        int gx = x + (n % WIN) - RAD;
        bool valid = (gy >= 0) & (gy < HS) & (gx >= 0) & (gx < WS);
        sc[n] = valid ? sc[n] * scale : -1e30f;
        m = fmaxf(m, sc[n]);
    }
    float ssum = 0.0f;
    #pragma unroll
    for (int n = 0; n < KN; n++) {
        sc[n] = __expf(sc[n] - m);
        ssum += sc[n];
    }
    const float inv = 1.0f / ssum;

    // ---------------- load V halo (reuse buffer) ----------------
    __syncthreads(); // everyone done reading K tile
    #pragma unroll 1
    for (int c = 0; c < DHEAD; c++) {
        const float* vc = vp + c * HWs;
        for (int p = tid; p < HALO_PIX; p += NTHR) {
            int hy = p / HALO_W;
            int hx = p - hy * HALO_W;
            int gy = tileY0 + hy - RAD;
            int gx = tileX0 + hx - RAD;
            float val = 0.0f;
            if (gy >= 0 && gy < HS && gx >= 0 && gx < WS)
                val = vc[gy * WS + gx];
            sT[c][p] = val;
        }
    }
    __syncthreads();

    // ---------------- pass 2: out = sum_n p_n * v_neighbor ----------------
    #pragma unroll 1
    for (int c = 0; c < DHEAD; c++) {
        const float* vb = &sT[c][hbase];
        float a0 = 0.0f, a1 = 0.0f, a2 = 0.0f, a3 = 0.0f;
        #pragma unroll
        for (int n = 0; n < KN; n += 4) {
            a0 = fmaf(sc[n], vb[(n / WIN) * HALO_W + (n % WIN)], a0);
            if (n + 1 < KN) a1 = fmaf(sc[n + 1], vb[((n + 1) / WIN) * HALO_W + ((n + 1) % WIN)], a1);
            if (n + 2 < KN) a2 = fmaf(sc[n + 2], vb[((n + 2) / WIN) * HALO_W + ((n + 2) % WIN)], a2);
            if (n + 3 < KN) a3 = fmaf(sc[n + 3], vb[((n + 3) / WIN) * HALO_W + ((n + 3) % WIN)], a3);
        }
        op[c * HWs + pix] = ((a0 + a1) + (a2 + a3)) * inv;
    }
}

extern "C" void kernel_launch(void* const* d_in, const int* in_sizes, int n_in,
                              void* d_out, int out_size)
{
    const float* q = (const float*)d_in[0];
    const float* k = (const float*)d_in[1];
    const float* v = (const float*)d_in[2];
    float* o = (float*)d_out;

    const int B = in_sizes[0] / (HEADS * DHEAD * HWs); // 4
    dim3 grid(WS / TX, HS / TY, B * HEADS);            // (3, 6, 32)
    dim3 block(TX, TY);                                // (16, 8)
    natten2d_kernel<<<grid, block>>>(q, k, v, o);
}